// round 4
// baseline (speedup 1.0000x reference)
#include <cuda_runtime.h>
#include <cuda_bf16.h>
#include <cstdint>

// Problem constants (shapes fixed by the dataset)
#define NMAX 50000
#define EMAX 600000
#define FH   128      // hidden = output feature width
#define BN_EPS 1e-5f

// ---------------- scratch (device globals; no allocation allowed) ----------
__device__ float g_h[(size_t)NMAX * FH];   // buffer A: h = x@W1, later h1 (post BN1)
__device__ float g_t[(size_t)NMAX * FH];   // buffer B: gcn pre-BN, later neigh
__device__ int   g_cnt[NMAX];              // in-degree (dst counts, no self loop)
__device__ int   g_fill[NMAX];             // bucket fill cursors
__device__ int   g_rowstart[NMAX + 1];     // CSR row offsets (by dst)
__device__ float g_dis[NMAX];              // deg^{-1/2}, deg = cnt+1 (self loop)
__device__ int   g_esrc[EMAX];             // CSR column indices (src node ids)
__device__ float g_sum[FH], g_sq[FH];      // BN reduction accumulators
__device__ float g_a[FH], g_b[FH];         // BN fused scale/shift

// ---------------- init ------------------------------------------------------
__global__ void zero_kernel(int n) {
    int i = blockIdx.x * blockDim.x + threadIdx.x;
    if (i < n) { g_cnt[i] = 0; g_fill[i] = 0; }
    if (i < FH) { g_sum[i] = 0.f; g_sq[i] = 0.f; }
}

__global__ void count_kernel(const int* __restrict__ dst, int E) {
    int e = blockIdx.x * blockDim.x + threadIdx.x;
    if (e < E) atomicAdd(&g_cnt[dst[e]], 1);
}

// Single-block exclusive scan over cnt -> rowstart; also dis = rsqrt(cnt+1)
__global__ void scan_kernel(int n) {
    __shared__ int s[1024];
    int tid = threadIdx.x;
    int carry = 0;
    int nch = (n + 1023) >> 10;
    for (int ch = 0; ch < nch; ch++) {
        int idx = (ch << 10) + tid;
        int v = (idx < n) ? g_cnt[idx] : 0;
        s[tid] = v;
        __syncthreads();
        #pragma unroll
        for (int off = 1; off < 1024; off <<= 1) {
            int t = (tid >= off) ? s[tid - off] : 0;
            __syncthreads();
            s[tid] += t;
            __syncthreads();
        }
        int inc = s[tid];
        if (idx < n) {
            g_rowstart[idx] = carry + inc - v;           // exclusive
            g_dis[idx] = rsqrtf((float)v + 1.0f);        // deg includes self loop
        }
        int tot = s[1023];
        __syncthreads();
        carry += tot;
    }
    if (tid == 0) g_rowstart[n] = carry;
}

__global__ void fill_kernel(const int* __restrict__ src, const int* __restrict__ dst, int E) {
    int e = blockIdx.x * blockDim.x + threadIdx.x;
    if (e < E) {
        int d = dst[e];
        int p = g_rowstart[d] + atomicAdd(&g_fill[d], 1);
        g_esrc[p] = src[e];
    }
}

// ---------------- SGEMM: C[M,128] = A1[:, :K1] @ Wa + A2[:, :KTOT-K1] @ Wb + bias
// 128x128 tile, BK=8, 256 threads, 8x8 register microtile.
template <int KTOT, int K1>
__global__ void __launch_bounds__(256) gemm_kernel(
    const float* __restrict__ A1, const float* __restrict__ A2,
    const float* __restrict__ Wa, const float* __restrict__ Wb,
    const float* __restrict__ bias, float* __restrict__ C, int M)
{
    __shared__ __align__(16) float As[8][128];
    __shared__ __align__(16) float Ws[8][128];
    const int tid = threadIdx.x;
    const int tx = tid & 15;        // col group
    const int ty = tid >> 4;        // row group
    const int row0 = blockIdx.x * 128;

    // A loader: each thread loads one float4: row lm, k-offset lk..lk+3
    const int lm = tid >> 1;
    const int lk = (tid & 1) * 4;
    // W loader: each thread loads one float4 of the 8x128 tile
    const int wk = tid >> 5;                 // 0..7
    const int wc = (tid * 4) & 127;

    float acc[8][8];
    #pragma unroll
    for (int i = 0; i < 8; i++)
        #pragma unroll
        for (int j = 0; j < 8; j++) acc[i][j] = 0.f;

    for (int kt = 0; kt < KTOT; kt += 8) {
        // load A tile (zero-fill out of range rows)
        float4 av = make_float4(0.f, 0.f, 0.f, 0.f);
        {
            int m = row0 + lm;
            int kg = kt + lk;
            if (m < M) {
                if (K1 == KTOT || kg < K1)
                    av = *(const float4*)(A1 + (size_t)m * K1 + kg);
                else
                    av = *(const float4*)(A2 + (size_t)m * (KTOT - K1) + (kg - K1));
            }
            As[lk + 0][lm] = av.x;
            As[lk + 1][lm] = av.y;
            As[lk + 2][lm] = av.z;
            As[lk + 3][lm] = av.w;
        }
        // load W tile
        {
            int kg = kt + wk;
            float4 wv;
            if (K1 == KTOT || kg < K1)
                wv = *(const float4*)(Wa + (size_t)kg * FH + wc);
            else
                wv = *(const float4*)(Wb + (size_t)(kg - K1) * FH + wc);
            *(float4*)&Ws[wk][wc] = wv;
        }
        __syncthreads();

        #pragma unroll
        for (int kk = 0; kk < 8; kk++) {
            const float4* ap = (const float4*)As[kk];
            const float4* wp = (const float4*)Ws[kk];
            float4 aA = ap[ty * 2], aB = ap[ty * 2 + 1];
            float4 wA = wp[tx * 2], wB = wp[tx * 2 + 1];
            float avr[8] = {aA.x, aA.y, aA.z, aA.w, aB.x, aB.y, aB.z, aB.w};
            float wvr[8] = {wA.x, wA.y, wA.z, wA.w, wB.x, wB.y, wB.z, wB.w};
            #pragma unroll
            for (int i = 0; i < 8; i++)
                #pragma unroll
                for (int j = 0; j < 8; j++)
                    acc[i][j] = fmaf(avr[i], wvr[j], acc[i][j]);
        }
        __syncthreads();
    }

    float4 bb0 = make_float4(0.f, 0.f, 0.f, 0.f), bb1 = bb0;
    if (bias) {
        bb0 = ((const float4*)bias)[tx * 2];
        bb1 = ((const float4*)bias)[tx * 2 + 1];
    }
    int mb = row0 + ty * 8;
    #pragma unroll
    for (int i = 0; i < 8; i++) {
        int m = mb + i;
        if (m < M) {
            float4* cp = (float4*)(C + (size_t)m * FH + tx * 8);
            float4 o0 = make_float4(acc[i][0] + bb0.x, acc[i][1] + bb0.y,
                                    acc[i][2] + bb0.z, acc[i][3] + bb0.w);
            float4 o1 = make_float4(acc[i][4] + bb1.x, acc[i][5] + bb1.y,
                                    acc[i][6] + bb1.z, acc[i][7] + bb1.w);
            cp[0] = o0;
            cp[1] = o1;
        }
    }
}

// ---------------- GCN aggregation: out[i] = sum_{s in N(i)} dis_i*dis_s*h[s]
//                                          + dis_i^2 * h[i] + b1
// one warp per node, 4 floats per lane, accumulators in registers.
__global__ void __launch_bounds__(256) gcn_agg_kernel(
    const float* __restrict__ h, const float* __restrict__ b1,
    float* __restrict__ out, int n)
{
    int wid = (blockIdx.x * blockDim.x + threadIdx.x) >> 5;
    int lane = threadIdx.x & 31;
    if (wid >= n) return;
    const float4* hv = (const float4*)h;
    float di = g_dis[wid];
    float4 hi = hv[(size_t)wid * 32 + lane];
    float w0 = di * di;
    float4 acc = make_float4(hi.x * w0, hi.y * w0, hi.z * w0, hi.w * w0);
    int beg = g_rowstart[wid], end = g_rowstart[wid + 1];
    for (int j = beg; j < end; j++) {
        int s = g_esrc[j];
        float w = di * g_dis[s];
        float4 hs = hv[(size_t)s * 32 + lane];
        acc.x = fmaf(w, hs.x, acc.x);
        acc.y = fmaf(w, hs.y, acc.y);
        acc.z = fmaf(w, hs.z, acc.z);
        acc.w = fmaf(w, hs.w, acc.w);
    }
    float4 bb = ((const float4*)b1)[lane];
    acc.x += bb.x; acc.y += bb.y; acc.z += bb.z; acc.w += bb.w;
    ((float4*)out)[(size_t)wid * 32 + lane] = acc;
}

// ---------------- SAGE mean aggregation: out[i] = mean_{s in N(i)} h1[s]
__global__ void __launch_bounds__(256) sage_agg_kernel(
    const float* __restrict__ h1, float* __restrict__ out, int n)
{
    int wid = (blockIdx.x * blockDim.x + threadIdx.x) >> 5;
    int lane = threadIdx.x & 31;
    if (wid >= n) return;
    const float4* hv = (const float4*)h1;
    float4 acc = make_float4(0.f, 0.f, 0.f, 0.f);
    int beg = g_rowstart[wid], end = g_rowstart[wid + 1];
    for (int j = beg; j < end; j++) {
        int s = g_esrc[j];
        float4 hs = hv[(size_t)s * 32 + lane];
        acc.x += hs.x; acc.y += hs.y; acc.z += hs.z; acc.w += hs.w;
    }
    int c = end - beg;
    float sc = 1.0f / fmaxf((float)c, 1.0f);
    acc.x *= sc; acc.y *= sc; acc.z *= sc; acc.w *= sc;
    ((float4*)out)[(size_t)wid * 32 + lane] = acc;
}

// ---------------- BatchNorm: column sums + sum of squares ------------------
__global__ void __launch_bounds__(512) bnstats_kernel(const float* __restrict__ v, int n) {
    __shared__ float ss[512], sq[512];
    int c = threadIdx.x & 127;
    int rr = threadIdx.x >> 7;          // 0..3
    float s = 0.f, q = 0.f;
    for (int r = blockIdx.x * 4 + rr; r < n; r += gridDim.x * 4) {
        float x = v[(size_t)r * FH + c];
        s += x;
        q = fmaf(x, x, q);
    }
    ss[threadIdx.x] = s;
    sq[threadIdx.x] = q;
    __syncthreads();
    if (rr == 0) {
        s = ss[c] + ss[c + 128] + ss[c + 256] + ss[c + 384];
        q = sq[c] + sq[c + 128] + sq[c + 256] + sq[c + 384];
        atomicAdd(&g_sum[c], s);
        atomicAdd(&g_sq[c], q);
    }
}

// compute fused scale/shift, then reset accumulators for the next BN pass
__global__ void bnfinal_kernel(const float* __restrict__ gamma,
                               const float* __restrict__ beta, int n) {
    int c = threadIdx.x;
    float invN = 1.0f / (float)n;
    float mean = g_sum[c] * invN;
    float var = g_sq[c] * invN - mean * mean;
    float a = gamma[c] * rsqrtf(var + BN_EPS);
    g_a[c] = a;
    g_b[c] = beta[c] - mean * a;
    g_sum[c] = 0.f;
    g_sq[c] = 0.f;
}

// out = relu(a*in + b)  (elementwise, float4)
__global__ void __launch_bounds__(256) bnapply_kernel(
    const float* __restrict__ in, float* __restrict__ out, int n4)
{
    int i = blockIdx.x * blockDim.x + threadIdx.x;
    if (i >= n4) return;
    int c4 = i & 31;
    float4 v = ((const float4*)in)[i];
    float4 a = ((const float4*)g_a)[c4];
    float4 b = ((const float4*)g_b)[c4];
    float4 o;
    o.x = fmaxf(fmaf(a.x, v.x, b.x), 0.f);
    o.y = fmaxf(fmaf(a.y, v.y, b.y), 0.f);
    o.z = fmaxf(fmaf(a.z, v.z, b.z), 0.f);
    o.w = fmaxf(fmaf(a.w, v.w, b.w), 0.f);
    ((float4*)out)[i] = o;
}

// ---------------- host orchestration ---------------------------------------
extern "C" void kernel_launch(void* const* d_in, const int* in_sizes, int n_in,
                              void* d_out, int out_size) {
    const float* x      = (const float*)d_in[0];
    const int*   ei     = (const int*)  d_in[1];
    const float* W1     = (const float*)d_in[2];
    const float* b1     = (const float*)d_in[3];
    const float* gamma1 = (const float*)d_in[4];
    const float* beta1  = (const float*)d_in[5];
    const float* Wl     = (const float*)d_in[6];
    const float* bl     = (const float*)d_in[7];
    const float* Wr     = (const float*)d_in[8];
    const float* gamma2 = (const float*)d_in[9];
    const float* beta2  = (const float*)d_in[10];

    const int N = in_sizes[0] / 64;     // 50000
    const int E = in_sizes[1] / 2;      // 600000
    const int* src = ei;
    const int* dst = ei + E;

    float* out = (float*)d_out;

    float *hbuf, *tbuf;
    cudaGetSymbolAddress((void**)&hbuf, g_h);
    cudaGetSymbolAddress((void**)&tbuf, g_t);

    const int TB = 256;
    int gN   = (N + TB - 1) / TB;
    int gE   = (E + TB - 1) / TB;
    int gWpN = (N * 32 + TB - 1) / TB;          // warp-per-node grids
    int gElt = (N * 32 + TB - 1) / TB;          // N*128/4 float4 elements
    int gGemm = (N + 127) / 128;

    // CSR build
    zero_kernel<<<gN, TB>>>(N);
    count_kernel<<<gE, TB>>>(dst, E);
    scan_kernel<<<1, 1024>>>(N);
    fill_kernel<<<gE, TB>>>(src, dst, E);

    // h = x @ W1
    gemm_kernel<64, 64><<<gGemm, TB>>>(x, nullptr, W1, nullptr, nullptr, hbuf, N);

    // GCN aggregate (+b1) -> tbuf ; BN1 ; relu -> hbuf
    gcn_agg_kernel<<<gWpN, TB>>>(hbuf, b1, tbuf, N);
    bnstats_kernel<<<512, 512>>>(tbuf, N);
    bnfinal_kernel<<<1, 128>>>(gamma1, beta1, N);
    bnapply_kernel<<<gElt, TB>>>(tbuf, hbuf, N * 32);

    // SAGE mean aggregate -> tbuf (neigh)
    sage_agg_kernel<<<gWpN, TB>>>(hbuf, tbuf, N);

    // out_pre = neigh@Wl + h1@Wr + bl  -> d_out
    gemm_kernel<256, 128><<<gGemm, TB>>>(tbuf, hbuf, Wl, Wr, bl, out, N);

    // BN2 ; relu in place on d_out
    bnstats_kernel<<<512, 512>>>(out, N);
    bnfinal_kernel<<<1, 128>>>(gamma2, beta2, N);
    bnapply_kernel<<<gElt, TB>>>(out, out, N * 32);
}

// round 9
// speedup vs baseline: 1.3660x; 1.3660x over previous
#include <cuda_runtime.h>
#include <cuda_bf16.h>
#include <cstdint>

// Problem constants (shapes fixed by the dataset)
#define NMAX 50000
#define EMAX 600000
#define FH   128      // hidden = output feature width
#define BN_EPS 1e-5f

// ---------------- scratch (device globals; no allocation allowed) ----------
__device__ float g_h[(size_t)NMAX * FH];   // buffer A: h = x@W1, later h1 (post BN1)
__device__ float g_t[(size_t)NMAX * FH];   // buffer B: gcn pre-BN, later neigh
__device__ int   g_cnt[NMAX];              // in-degree (self-restores to 0 each call)
__device__ int   g_rowstart[NMAX + 1];     // CSR row offsets (by dst)
__device__ float g_dis[NMAX];              // deg^{-1/2}, deg = cnt+1 (self loop)
__device__ int   g_esrc[EMAX];             // CSR column indices (src node ids)
__device__ int   g_blksum[128];            // scan phase-1 block totals
__device__ int   g_blkoff[129];            // scan phase-2 exclusive offsets
__device__ float g_sum[FH], g_sq[FH];      // BN accumulators (reset by bnfinal)
__device__ float g_a[FH], g_b[FH];         // BN fused scale/shift

// ---------------- f32x2 helpers --------------------------------------------
__device__ __forceinline__ unsigned long long pack2(float lo, float hi) {
    unsigned long long r;
    asm("mov.b64 %0, {%1, %2};" : "=l"(r) : "f"(lo), "f"(hi));
    return r;
}
__device__ __forceinline__ unsigned long long dup2(float v) {
    unsigned long long r;
    asm("mov.b64 %0, {%1, %1};" : "=l"(r) : "f"(v));
    return r;
}
__device__ __forceinline__ void fma2(unsigned long long& acc,
                                     unsigned long long a, unsigned long long b) {
    asm("fma.rn.f32x2 %0, %1, %2, %0;" : "+l"(acc) : "l"(a), "l"(b));
}
__device__ __forceinline__ void unpack2(unsigned long long v, float& lo, float& hi) {
    asm("mov.b64 {%0, %1}, %2;" : "=f"(lo), "=f"(hi) : "l"(v));
}

// ---------------- CSR build -------------------------------------------------
__global__ void count_kernel(const int* __restrict__ dst, int E) {
    int e0 = (blockIdx.x * blockDim.x + threadIdx.x) * 4;
    if (e0 >= E) return;
    int4 d4 = *(const int4*)(dst + e0);
    atomicAdd(&g_cnt[d4.x], 1);
    if (e0 + 1 < E) atomicAdd(&g_cnt[d4.y], 1);
    if (e0 + 2 < E) atomicAdd(&g_cnt[d4.z], 1);
    if (e0 + 3 < E) atomicAdd(&g_cnt[d4.w], 1);
}

// phase 1: per-block (512) exclusive scan of counts; also writes dis
__global__ void __launch_bounds__(512) scan1_kernel(int n) {
    __shared__ int wsum[16];
    int idx = blockIdx.x * 512 + threadIdx.x;
    int v = (idx < n) ? g_cnt[idx] : 0;
    int lane = threadIdx.x & 31, w = threadIdx.x >> 5;
    int incl = v;
    #pragma unroll
    for (int o = 1; o < 32; o <<= 1) {
        int t = __shfl_up_sync(0xFFFFFFFFu, incl, o);
        if (lane >= o) incl += t;
    }
    if (lane == 31) wsum[w] = incl;
    __syncthreads();
    if (w == 0) {
        int s = (lane < 16) ? wsum[lane] : 0;
        #pragma unroll
        for (int o = 1; o < 16; o <<= 1) {
            int t = __shfl_up_sync(0xFFFFFFFFu, s, o);
            if (lane >= o) s += t;
        }
        if (lane < 16) wsum[lane] = s;
    }
    __syncthreads();
    int blockincl = incl + (w > 0 ? wsum[w - 1] : 0);
    if (idx < n) {
        g_rowstart[idx] = blockincl - v;                 // block-local exclusive
        g_dis[idx] = rsqrtf((float)v + 1.0f);            // deg includes self loop
    }
    if (threadIdx.x == 511) g_blksum[blockIdx.x] = blockincl;
}

// phase 2: scan of <=128 block sums
__global__ void scan2_kernel(int nb) {
    __shared__ int ws[4];
    int t = threadIdx.x;                                  // 128 threads
    int v = (t < nb) ? g_blksum[t] : 0;
    int lane = t & 31, w = t >> 5;
    int incl = v;
    #pragma unroll
    for (int o = 1; o < 32; o <<= 1) {
        int x = __shfl_up_sync(0xFFFFFFFFu, incl, o);
        if (lane >= o) incl += x;
    }
    if (lane == 31) ws[w] = incl;
    __syncthreads();
    int add = 0;
    for (int i = 0; i < w; i++) add += ws[i];
    incl += add;
    if (t < nb) g_blkoff[t] = incl - v;                   // exclusive
    if (t == nb - 1) g_blkoff[nb] = incl;                 // grand total
}

// phase 3: apply block offsets
__global__ void __launch_bounds__(512) scan3_kernel(int n, int nb) {
    int idx = blockIdx.x * 512 + threadIdx.x;
    if (idx < n) g_rowstart[idx] += g_blkoff[blockIdx.x];
    if (idx == 0) g_rowstart[n] = g_blkoff[nb];
}

// bucket fill; atomicSub returns counts to exactly 0 for the next call
__global__ void fill_kernel(const int* __restrict__ src, const int* __restrict__ dst, int E) {
    int e0 = (blockIdx.x * blockDim.x + threadIdx.x) * 4;
    if (e0 >= E) return;
    int4 d4 = *(const int4*)(dst + e0);
    int4 s4 = *(const int4*)(src + e0);
    int d[4] = {d4.x, d4.y, d4.z, d4.w};
    int s[4] = {s4.x, s4.y, s4.z, s4.w};
    #pragma unroll
    for (int k = 0; k < 4; k++) {
        if (e0 + k < E) {
            int p = g_rowstart[d[k]] + atomicSub(&g_cnt[d[k]], 1) - 1;
            g_esrc[p] = s[k];
        }
    }
}

// ---------------- SGEMM: C[M,128] = A1[:, :K1] @ Wa + A2[:, :KTOT-K1] @ Wb + bias
// 128x128 tile, BK=8, 256 threads, 8x8 microtile using packed fma.rn.f32x2.
template <int KTOT, int K1>
__global__ void __launch_bounds__(256) gemm_kernel(
    const float* __restrict__ A1, const float* __restrict__ A2,
    const float* __restrict__ Wa, const float* __restrict__ Wb,
    const float* __restrict__ bias, float* __restrict__ C, int M)
{
    __shared__ __align__(16) float As[8][128];
    __shared__ __align__(16) float Ws[8][128];
    const int tid = threadIdx.x;
    const int tx = tid & 15;        // col group
    const int ty = tid >> 4;        // row group
    const int row0 = blockIdx.x * 128;

    const int lm = tid >> 1;
    const int lk = (tid & 1) * 4;
    const int wk = tid >> 5;                 // 0..7
    const int wc = (tid * 4) & 127;

    unsigned long long accp[8][4];
    #pragma unroll
    for (int i = 0; i < 8; i++)
        #pragma unroll
        for (int j = 0; j < 4; j++) accp[i][j] = 0ULL;

    for (int kt = 0; kt < KTOT; kt += 8) {
        // load A tile (zero-fill out of range rows)
        float4 av = make_float4(0.f, 0.f, 0.f, 0.f);
        {
            int m = row0 + lm;
            int kg = kt + lk;
            if (m < M) {
                if (K1 == KTOT || kg < K1)
                    av = *(const float4*)(A1 + (size_t)m * K1 + kg);
                else
                    av = *(const float4*)(A2 + (size_t)m * (KTOT - K1) + (kg - K1));
            }
            As[lk + 0][lm] = av.x;
            As[lk + 1][lm] = av.y;
            As[lk + 2][lm] = av.z;
            As[lk + 3][lm] = av.w;
        }
        // load W tile
        {
            int kg = kt + wk;
            float4 wv;
            if (K1 == KTOT || kg < K1)
                wv = *(const float4*)(Wa + (size_t)kg * FH + wc);
            else
                wv = *(const float4*)(Wb + (size_t)(kg - K1) * FH + wc);
            *(float4*)&Ws[wk][wc] = wv;
        }
        __syncthreads();

        #pragma unroll
        for (int kk = 0; kk < 8; kk++) {
            const float4* ap = (const float4*)As[kk];
            const float4* wp = (const float4*)Ws[kk];
            float4 aA = ap[ty * 2], aB = ap[ty * 2 + 1];
            float4 wA = wp[tx * 2], wB = wp[tx * 2 + 1];
            unsigned long long wq0 = pack2(wA.x, wA.y);
            unsigned long long wq1 = pack2(wA.z, wA.w);
            unsigned long long wq2 = pack2(wB.x, wB.y);
            unsigned long long wq3 = pack2(wB.z, wB.w);
            float a_[8] = {aA.x, aA.y, aA.z, aA.w, aB.x, aB.y, aB.z, aB.w};
            #pragma unroll
            for (int i = 0; i < 8; i++) {
                unsigned long long apk = dup2(a_[i]);
                fma2(accp[i][0], apk, wq0);
                fma2(accp[i][1], apk, wq1);
                fma2(accp[i][2], apk, wq2);
                fma2(accp[i][3], apk, wq3);
            }
        }
        __syncthreads();
    }

    float4 bb0 = make_float4(0.f, 0.f, 0.f, 0.f), bb1 = bb0;
    if (bias) {
        bb0 = ((const float4*)bias)[tx * 2];
        bb1 = ((const float4*)bias)[tx * 2 + 1];
    }
    int mb = row0 + ty * 8;
    #pragma unroll
    for (int i = 0; i < 8; i++) {
        int m = mb + i;
        if (m < M) {
            float r[8];
            unpack2(accp[i][0], r[0], r[1]);
            unpack2(accp[i][1], r[2], r[3]);
            unpack2(accp[i][2], r[4], r[5]);
            unpack2(accp[i][3], r[6], r[7]);
            float4* cp = (float4*)(C + (size_t)m * FH + tx * 8);
            cp[0] = make_float4(r[0] + bb0.x, r[1] + bb0.y, r[2] + bb0.z, r[3] + bb0.w);
            cp[1] = make_float4(r[4] + bb1.x, r[5] + bb1.y, r[6] + bb1.z, r[7] + bb1.w);
        }
    }
}

// ---------------- GCN aggregation: out[i] = sum_{s in N(i)} dis_i*dis_s*h[s]
//                                          + dis_i^2 * h[i] + b1
// one warp per node, 4 floats per lane, 2x unrolled gathers for MLP.
__global__ void __launch_bounds__(256) gcn_agg_kernel(
    const float* __restrict__ h, const float* __restrict__ b1,
    float* __restrict__ out, int n)
{
    int wid = (blockIdx.x * blockDim.x + threadIdx.x) >> 5;
    int lane = threadIdx.x & 31;
    if (wid >= n) return;
    const float4* hv = (const float4*)h;
    float di = g_dis[wid];
    float4 hi = hv[(size_t)wid * 32 + lane];
    float w0 = di * di;
    float4 acc = make_float4(hi.x * w0, hi.y * w0, hi.z * w0, hi.w * w0);
    int beg = g_rowstart[wid], end = g_rowstart[wid + 1];
    int j = beg;
    int m2 = beg + ((end - beg) & ~1);
    for (; j < m2; j += 2) {
        int s0 = g_esrc[j], s1 = g_esrc[j + 1];
        float4 h0 = hv[(size_t)s0 * 32 + lane];
        float4 h1 = hv[(size_t)s1 * 32 + lane];
        float wgt0 = di * g_dis[s0];
        float wgt1 = di * g_dis[s1];
        acc.x = fmaf(wgt0, h0.x, acc.x);
        acc.y = fmaf(wgt0, h0.y, acc.y);
        acc.z = fmaf(wgt0, h0.z, acc.z);
        acc.w = fmaf(wgt0, h0.w, acc.w);
        acc.x = fmaf(wgt1, h1.x, acc.x);
        acc.y = fmaf(wgt1, h1.y, acc.y);
        acc.z = fmaf(wgt1, h1.z, acc.z);
        acc.w = fmaf(wgt1, h1.w, acc.w);
    }
    if (j < end) {
        int s = g_esrc[j];
        float w = di * g_dis[s];
        float4 hs = hv[(size_t)s * 32 + lane];
        acc.x = fmaf(w, hs.x, acc.x);
        acc.y = fmaf(w, hs.y, acc.y);
        acc.z = fmaf(w, hs.z, acc.z);
        acc.w = fmaf(w, hs.w, acc.w);
    }
    float4 bb = ((const float4*)b1)[lane];
    acc.x += bb.x; acc.y += bb.y; acc.z += bb.z; acc.w += bb.w;
    ((float4*)out)[(size_t)wid * 32 + lane] = acc;
}

// ---------------- SAGE mean aggregation: out[i] = mean_{s in N(i)} h1[s]
__global__ void __launch_bounds__(256) sage_agg_kernel(
    const float* __restrict__ h1, float* __restrict__ out, int n)
{
    int wid = (blockIdx.x * blockDim.x + threadIdx.x) >> 5;
    int lane = threadIdx.x & 31;
    if (wid >= n) return;
    const float4* hv = (const float4*)h1;
    float4 acc = make_float4(0.f, 0.f, 0.f, 0.f);
    int beg = g_rowstart[wid], end = g_rowstart[wid + 1];
    int j = beg;
    int m2 = beg + ((end - beg) & ~1);
    for (; j < m2; j += 2) {
        int s0 = g_esrc[j], s1 = g_esrc[j + 1];
        float4 h0 = hv[(size_t)s0 * 32 + lane];
        float4 h1v = hv[(size_t)s1 * 32 + lane];
        acc.x += h0.x + h1v.x;
        acc.y += h0.y + h1v.y;
        acc.z += h0.z + h1v.z;
        acc.w += h0.w + h1v.w;
    }
    if (j < end) {
        int s = g_esrc[j];
        float4 hs = hv[(size_t)s * 32 + lane];
        acc.x += hs.x; acc.y += hs.y; acc.z += hs.z; acc.w += hs.w;
    }
    int c = end - beg;
    float sc = 1.0f / fmaxf((float)c, 1.0f);
    acc.x *= sc; acc.y *= sc; acc.z *= sc; acc.w *= sc;
    ((float4*)out)[(size_t)wid * 32 + lane] = acc;
}

// ---------------- BatchNorm: column sums + sum of squares ------------------
__global__ void __launch_bounds__(512) bnstats_kernel(const float* __restrict__ v, int n) {
    __shared__ float ss[512], sq[512];
    int c = threadIdx.x & 127;
    int rr = threadIdx.x >> 7;          // 0..3
    float s = 0.f, q = 0.f;
    for (int r = blockIdx.x * 4 + rr; r < n; r += gridDim.x * 4) {
        float x = v[(size_t)r * FH + c];
        s += x;
        q = fmaf(x, x, q);
    }
    ss[threadIdx.x] = s;
    sq[threadIdx.x] = q;
    __syncthreads();
    if (rr == 0) {
        s = ss[c] + ss[c + 128] + ss[c + 256] + ss[c + 384];
        q = sq[c] + sq[c + 128] + sq[c + 256] + sq[c + 384];
        atomicAdd(&g_sum[c], s);
        atomicAdd(&g_sq[c], q);
    }
}

// compute fused scale/shift, then reset accumulators for the next BN pass
__global__ void bnfinal_kernel(const float* __restrict__ gamma,
                               const float* __restrict__ beta, int n) {
    int c = threadIdx.x;
    float invN = 1.0f / (float)n;
    float mean = g_sum[c] * invN;
    float var = g_sq[c] * invN - mean * mean;
    float a = gamma[c] * rsqrtf(var + BN_EPS);
    g_a[c] = a;
    g_b[c] = beta[c] - mean * a;
    g_sum[c] = 0.f;
    g_sq[c] = 0.f;
}

// out = relu(a*in + b)  (elementwise, float4)
__global__ void __launch_bounds__(256) bnapply_kernel(
    const float* __restrict__ in, float* __restrict__ out, int n4)
{
    int i = blockIdx.x * blockDim.x + threadIdx.x;
    if (i >= n4) return;
    int c4 = i & 31;
    float4 v = ((const float4*)in)[i];
    float4 a = ((const float4*)g_a)[c4];
    float4 b = ((const float4*)g_b)[c4];
    float4 o;
    o.x = fmaxf(fmaf(a.x, v.x, b.x), 0.f);
    o.y = fmaxf(fmaf(a.y, v.y, b.y), 0.f);
    o.z = fmaxf(fmaf(a.z, v.z, b.z), 0.f);
    o.w = fmaxf(fmaf(a.w, v.w, b.w), 0.f);
    ((float4*)out)[i] = o;
}

// ---------------- host orchestration ---------------------------------------
extern "C" void kernel_launch(void* const* d_in, const int* in_sizes, int n_in,
                              void* d_out, int out_size) {
    const float* x      = (const float*)d_in[0];
    const int*   ei     = (const int*)  d_in[1];
    const float* W1     = (const float*)d_in[2];
    const float* b1     = (const float*)d_in[3];
    const float* gamma1 = (const float*)d_in[4];
    const float* beta1  = (const float*)d_in[5];
    const float* Wl     = (const float*)d_in[6];
    const float* bl     = (const float*)d_in[7];
    const float* Wr     = (const float*)d_in[8];
    const float* gamma2 = (const float*)d_in[9];
    const float* beta2  = (const float*)d_in[10];

    const int N = in_sizes[0] / 64;     // 50000
    const int E = in_sizes[1] / 2;      // 600000
    const int* src = ei;
    const int* dst = ei + E;

    float* out = (float*)d_out;

    float *hbuf, *tbuf;
    cudaGetSymbolAddress((void**)&hbuf, g_h);
    cudaGetSymbolAddress((void**)&tbuf, g_t);

    const int TB = 256;
    int gE4  = ((E + 3) / 4 + TB - 1) / TB;     // 4 edges per thread
    int nb   = (N + 511) / 512;                  // scan blocks (98 <= 128)
    int gWpN = (N * 32 + TB - 1) / TB;          // warp-per-node grids
    int gElt = (N * 32 + TB - 1) / TB;          // N*128/4 float4 elements
    int gGemm = (N + 127) / 128;

    // CSR build (g_cnt enters and leaves at all-zero; no zero kernel needed)
    count_kernel<<<gE4, TB>>>(dst, E);
    scan1_kernel<<<nb, 512>>>(N);
    scan2_kernel<<<1, 128>>>(nb);
    scan3_kernel<<<nb, 512>>>(N, nb);
    fill_kernel<<<gE4, TB>>>(src, dst, E);

    // h = x @ W1
    gemm_kernel<64, 64><<<gGemm, TB>>>(x, nullptr, W1, nullptr, nullptr, hbuf, N);

    // GCN aggregate (+b1) -> tbuf ; BN1 ; relu -> hbuf
    gcn_agg_kernel<<<gWpN, TB>>>(hbuf, b1, tbuf, N);
    bnstats_kernel<<<512, 512>>>(tbuf, N);
    bnfinal_kernel<<<1, 128>>>(gamma1, beta1, N);
    bnapply_kernel<<<gElt, TB>>>(tbuf, hbuf, N * 32);

    // SAGE mean aggregate -> tbuf (neigh)
    sage_agg_kernel<<<gWpN, TB>>>(hbuf, tbuf, N);

    // out_pre = neigh@Wl + h1@Wr + bl  -> d_out
    gemm_kernel<256, 128><<<gGemm, TB>>>(tbuf, hbuf, Wl, Wr, bl, out, N);

    // BN2 ; relu in place on d_out
    bnstats_kernel<<<512, 512>>>(out, N);
    bnfinal_kernel<<<1, 128>>>(gamma2, beta2, N);
    bnapply_kernel<<<gElt, TB>>>(out, out, N * 32);
}